// round 14
// baseline (speedup 1.0000x reference)
#include <cuda_runtime.h>
#include <cuda_fp16.h>
#include <cstdint>

#define NUM_USERS 100000
#define NUM_ITEMS 200000
#define NN        (NUM_USERS + NUM_ITEMS)   // 300000
#define D         64
#define UD        (NUM_USERS * D)           // 6400000
#define NNZ       5000000
#define BATCH     16384
#define WIDTH     32                         // ELL width (P(deg>32) ~ 1e-4, spill net)
#define MAX_SPILL 2048
#define FILL_BLOCKS 4883                     // ceil(NNZ/4/256)
#define CONV_BLOCKS 9375                     // NN*D/8/256 exactly

// fp16 embeddings: e0 (converted), layer-1, layer-2 outputs (38.4 MB each)
__device__ __half g_E0[(size_t)NN * D];
__device__ __half g_A[(size_t)NN * D];
__device__ __half g_B[(size_t)NN * D];

// ELL storage: packed (col, half2(val,val) bits). 76.8 MB (L2-resident)
__device__ int2 g_ell[(size_t)NN * WIDTH];
__device__ int  g_len[NN];

// Spill safety net (degree > WIDTH; expected ~tens of edges)
__device__ int   g_spill_count;
__device__ int   g_srow[MAX_SPILL];
__device__ int   g_scol[MAX_SPILL];
__device__ float g_sval[MAX_SPILL];

// ---------------------------------------------------------------------------
__global__ void init_kernel() {
    int i = blockIdx.x * blockDim.x + threadIdx.x;
    const int n4 = NN / 4;                    // 75000
    if (i < n4)
        reinterpret_cast<int4*>(g_len)[i] = make_int4(0, 0, 0, 0);
    if (i == 0) g_spill_count = 0;
}

// Combined build kernel: blocks [0, FILL_BLOCKS) run ELL fill (atomic-bound),
// blocks [FILL_BLOCKS, +CONV_BLOCKS) run fp32->fp16 convert (DRAM-bound).
__global__ void build_kernel(const int*   __restrict__ erow,
                             const int*   __restrict__ ecol,
                             const float* __restrict__ evals,
                             const float* __restrict__ uemb,
                             const float* __restrict__ iemb) {
    if (blockIdx.x < FILL_BLOCKS) {
        int t = blockIdx.x * blockDim.x + threadIdx.x;
        int i4 = t * 4;
        if (i4 >= NNZ) return;
        int4   r = __ldcs(reinterpret_cast<const int4*>(erow + i4));
        int4   c = __ldcs(reinterpret_cast<const int4*>(ecol + i4));
        float4 v = __ldcs(reinterpret_cast<const float4*>(evals + i4));
        int    rows[4] = {r.x, r.y, r.z, r.w};
        int    cols[4] = {c.x, c.y, c.z, c.w};
        float  vals[4] = {v.x, v.y, v.z, v.w};
#pragma unroll
        for (int k = 0; k < 4; k++) {
            int pos = atomicAdd(&g_len[rows[k]], 1);
            if (pos < WIDTH) {
                __half2 vh = __floats2half2_rn(vals[k], vals[k]);
                g_ell[(size_t)rows[k] * WIDTH + pos] =
                    make_int2(cols[k], *reinterpret_cast<int*>(&vh));
            } else {
                int s = atomicAdd(&g_spill_count, 1);
                if (s < MAX_SPILL) {
                    g_srow[s] = rows[k]; g_scol[s] = cols[k]; g_sval[s] = vals[k];
                }
            }
        }
    } else {
        long long i8 = ((long long)(blockIdx.x - FILL_BLOCKS) * blockDim.x
                        + threadIdx.x) * 8;
        if (i8 >= (long long)NN * D) return;
        const float* src = (i8 < UD) ? (uemb + i8) : (iemb + (i8 - UD));
        float4 a = *reinterpret_cast<const float4*>(src);
        float4 b = *reinterpret_cast<const float4*>(src + 4);
        __half2 h0 = __floats2half2_rn(a.x, a.y);
        __half2 h1 = __floats2half2_rn(a.z, a.w);
        __half2 h2 = __floats2half2_rn(b.x, b.y);
        __half2 h3 = __floats2half2_rn(b.z, b.w);
        uint4 packed = make_uint4(*reinterpret_cast<uint32_t*>(&h0),
                                  *reinterpret_cast<uint32_t*>(&h1),
                                  *reinterpret_cast<uint32_t*>(&h2),
                                  *reinterpret_cast<uint32_t*>(&h3));
        *reinterpret_cast<uint4*>(g_E0 + i8) = packed;
    }
}

// ---------------------------------------------------------------------------
// Warp computes one output row. 16 lanes per edge, lane owns dims
// {4*sub .. 4*sub+3}; halves process alternating edges. Accumulation via
// HFMA2 into half2, flushed to fp32 every 8 edges (bounds fp16 error).
// Padding edges carry c=0, v=half2(0,0): load row 0 (L1-hot), HFMA adds 0.
// Returns float4 (reduced across halves; identical in lane and lane^16).
__device__ __forceinline__ float4 spmm_row_acc_h(int node, int lane,
                                                 const __half* __restrict__ src) {
    int n = min(g_len[node], WIDTH);
    int sub  = lane & 15;
    int half_id = lane >> 4;

    int2 ev = make_int2(0, 0);
    if (lane < n)
        ev = __ldcs(g_ell + (size_t)node * WIDTH + lane);  // evict-first stream

    float4 acc = make_float4(0.f, 0.f, 0.f, 0.f);
    int n8 = (n + 7) & ~7;                    // <= 32
    for (int j = 0; j < n8; j += 8) {
        __half2 a01 = __float2half2_rn(0.f);
        __half2 a23 = __float2half2_rn(0.f);
#pragma unroll
        for (int k = 0; k < 4; k++) {
            int idx = j + 2 * k + half_id;    // this half's edge
            int cj = __shfl_sync(0xFFFFFFFFu, ev.x, idx);
            int vb = __shfl_sync(0xFFFFFFFFu, ev.y, idx);
            __half2 vj2 = *reinterpret_cast<__half2*>(&vb);
            uint2 raw = *reinterpret_cast<const uint2*>(
                src + (size_t)cj * D + 4 * sub);
            a01 = __hfma2(*reinterpret_cast<__half2*>(&raw.x), vj2, a01);
            a23 = __hfma2(*reinterpret_cast<__half2*>(&raw.y), vj2, a23);
        }
        float2 f01 = __half22float2(a01);
        float2 f23 = __half22float2(a23);
        acc.x += f01.x;
        acc.y += f01.y;
        acc.z += f23.x;
        acc.w += f23.y;
    }
    // cross-half reduce: lanes L and L^16 hold partials for the same dims
    acc.x += __shfl_xor_sync(0xFFFFFFFFu, acc.x, 16);
    acc.y += __shfl_xor_sync(0xFFFFFFFFu, acc.y, 16);
    acc.z += __shfl_xor_sync(0xFFFFFFFFu, acc.z, 16);
    acc.w += __shfl_xor_sync(0xFFFFFFFFu, acc.w, 16);
    return acc;
}

// Rare-path (post-reduce): add spill contributions for rows deg > WIDTH.
__device__ __forceinline__ float4 spill_patch_h(int node, int lane, float4 acc,
                                                const __half* __restrict__ src) {
    if (g_len[node] > WIDTH) {                 // ~25 rows in the whole graph
        int sub = lane & 15;
        int cnt = min(g_spill_count, MAX_SPILL);
        for (int s = 0; s < cnt; s++) {
            if (g_srow[s] == node) {
                int   cj = g_scol[s];
                float vj = g_sval[s];
                uint2 raw = *reinterpret_cast<const uint2*>(
                    src + (size_t)cj * D + 4 * sub);
                float2 x0 = __half22float2(*reinterpret_cast<__half2*>(&raw.x));
                float2 x1 = __half22float2(*reinterpret_cast<__half2*>(&raw.y));
                acc.x += vj * x0.x;
                acc.y += vj * x0.y;
                acc.z += vj * x1.x;
                acc.w += vj * x1.y;
            }
        }
    }
    return acc;
}

// Full SpMM (layers 1, 2): one warp per destination row; lanes<16 store 8B each.
__global__ void spmm_ell_kernel(int stage) {
    int warp = (blockIdx.x * blockDim.x + threadIdx.x) >> 5;
    int lane = threadIdx.x & 31;
    if (warp >= NN) return;

    const __half* src = (stage == 0) ? g_E0 : g_A;
    __half*       dst = (stage == 0) ? g_A  : g_B;

    float4 acc = spmm_row_acc_h(warp, lane, src);

    if (lane < 16) {
        __half2 h0 = __floats2half2_rn(acc.x, acc.y);
        __half2 h1 = __floats2half2_rn(acc.z, acc.w);
        uint32_t b0 = *reinterpret_cast<uint32_t*>(&h0);
        uint32_t b1 = *reinterpret_cast<uint32_t*>(&h1);
        asm volatile("st.global.cs.v2.b32 [%0], {%1, %2};"
                     :: "l"(dst + (size_t)warp * D + 4 * lane), "r"(b0), "r"(b1)
                     : "memory");
    }
}

// Spill mop-up (tiny grid, usually no-op): 16 threads/edge, 4 dims each.
__global__ void spill_kernel(int stage) {
    int cnt = min(g_spill_count, MAX_SPILL);
    int idx = blockIdx.x * blockDim.x + threadIdx.x;
    int e = idx >> 4;
    int q = idx & 15;
    if (e >= cnt) return;

    const __half* src = (stage == 0) ? g_E0 : g_A;
    __half*       dst = (stage == 0) ? g_A  : g_B;

    int   row = g_srow[e];
    int   col = g_scol[e];
    float v   = g_sval[e];
    const __half* srow = src + (size_t)col * D + q * 4;
    __half* p = dst + (size_t)row * D + q * 4;
#pragma unroll
    for (int h = 0; h < 2; h++) {
        uint32_t raw = *reinterpret_cast<const uint32_t*>(srow + 2 * h);
        float2 x = __half22float2(*reinterpret_cast<__half2*>(&raw));
        __half2 m = __floats2half2_rn(v * x.x, v * x.y);
        uint32_t mb = *reinterpret_cast<uint32_t*>(&m);
        asm volatile("red.global.add.noftz.f16x2 [%0], %1;"
                     :: "l"(p + 2 * h), "r"(mb) : "memory");
    }
}

// ---------------------------------------------------------------------------
// Fused layer-3 + dot: one warp per pair. e3 computed inline from g_B (fp16).
// e0 endpoint terms read exact fp32 inputs. Lanes<16 own 4 dims each.
__global__ void final_kernel(const int*   __restrict__ users,
                             const int*   __restrict__ items,
                             const float* __restrict__ uemb,
                             const float* __restrict__ iemb,
                             float*       __restrict__ out) {
    int warp = (blockIdx.x * blockDim.x + threadIdx.x) >> 5;
    int lane = threadIdx.x & 31;
    if (warp >= BATCH) return;

    int u  = __ldg(users + warp);
    int it = __ldg(items + warp);
    int nu = u;
    int ni = NUM_USERS + it;

    // e3 at the two endpoints (layer-3 SpMM, inline, fp16 gathers)
    float4 e3u = spmm_row_acc_h(nu, lane, g_B);
    e3u = spill_patch_h(nu, lane, e3u, g_B);
    float4 e3i = spmm_row_acc_h(ni, lane, g_B);
    e3i = spill_patch_h(ni, lane, e3i, g_B);

    float dot = 0.f;
    if (lane < 16) {
        int sub = lane;
        size_t urow = (size_t)nu * D + 4 * sub;
        size_t irow = (size_t)ni * D + 4 * sub;

        uint2 rauh = *reinterpret_cast<const uint2*>(g_A + urow);
        uint2 rbuh = *reinterpret_cast<const uint2*>(g_B + urow);
        uint2 raih = *reinterpret_cast<const uint2*>(g_A + irow);
        uint2 rbih = *reinterpret_cast<const uint2*>(g_B + irow);
        float4 e0u = *reinterpret_cast<const float4*>(uemb + (size_t)u  * D + 4 * sub);
        float4 e0i = *reinterpret_cast<const float4*>(iemb + (size_t)it * D + 4 * sub);

        float2 au0 = __half22float2(*reinterpret_cast<__half2*>(&rauh.x));
        float2 au1 = __half22float2(*reinterpret_cast<__half2*>(&rauh.y));
        float2 bu0 = __half22float2(*reinterpret_cast<__half2*>(&rbuh.x));
        float2 bu1 = __half22float2(*reinterpret_cast<__half2*>(&rbuh.y));
        float2 ai0 = __half22float2(*reinterpret_cast<__half2*>(&raih.x));
        float2 ai1 = __half22float2(*reinterpret_cast<__half2*>(&raih.y));
        float2 bi0 = __half22float2(*reinterpret_cast<__half2*>(&rbih.x));
        float2 bi1 = __half22float2(*reinterpret_cast<__half2*>(&rbih.y));

        float uv0 = e0u.x + au0.x + bu0.x + e3u.x;
        float uv1 = e0u.y + au0.y + bu0.y + e3u.y;
        float uv2 = e0u.z + au1.x + bu1.x + e3u.z;
        float uv3 = e0u.w + au1.y + bu1.y + e3u.w;
        float iv0 = e0i.x + ai0.x + bi0.x + e3i.x;
        float iv1 = e0i.y + ai0.y + bi0.y + e3i.y;
        float iv2 = e0i.z + ai1.x + bi1.x + e3i.z;
        float iv3 = e0i.w + ai1.y + bi1.y + e3i.w;

        dot = uv0 * iv0 + uv1 * iv1 + uv2 * iv2 + uv3 * iv3;
    }
#pragma unroll
    for (int off = 16; off > 0; off >>= 1)
        dot += __shfl_xor_sync(0xFFFFFFFFu, dot, off);

    if (lane == 0) out[warp] = dot * 0.0625f;   // (1/4)*(1/4)
}

// ---------------------------------------------------------------------------
extern "C" void kernel_launch(void* const* d_in, const int* in_sizes, int n_in,
                              void* d_out, int out_size) {
    const int*   users = (const int*)  d_in[0];
    const int*   items = (const int*)  d_in[1];
    const int*   erow  = (const int*)  d_in[2];
    const int*   ecol  = (const int*)  d_in[3];
    const float* evals = (const float*)d_in[4];
    const float* uemb  = (const float*)d_in[5];
    const float* iemb  = (const float*)d_in[6];
    float* out = (float*)d_out;

    // --- init, then overlapped ELL fill + fp16 convert ---
    init_kernel<<<(NN / 4 + 255) / 256, 256>>>();
    build_kernel<<<FILL_BLOCKS + CONV_BLOCKS, 256>>>(erow, ecol, evals, uemb, iemb);

    int threads = 256;                         // 8 warps/block
    int blocks  = (NN + 7) / 8;                // 37500
    int sblocks = (MAX_SPILL * 16) / 256;      // 128

    // --- layers 1,2 full; layer 3 fused into final ---
    spmm_ell_kernel<<<blocks, threads>>>(0);
    spill_kernel<<<sblocks, 256>>>(0);

    spmm_ell_kernel<<<blocks, threads>>>(1);
    spill_kernel<<<sblocks, 256>>>(1);

    // --- fused layer-3 + gather + dot ---
    final_kernel<<<(BATCH + 7) / 8, 256>>>(users, items, uemb, iemb, out);
}

// round 15
// speedup vs baseline: 1.1012x; 1.1012x over previous
#include <cuda_runtime.h>
#include <cuda_fp16.h>
#include <cstdint>

#define NUM_USERS 100000
#define NUM_ITEMS 200000
#define NN        (NUM_USERS + NUM_ITEMS)   // 300000
#define D         64
#define UD        (NUM_USERS * D)           // 6400000
#define NNZ       5000000
#define BATCH     16384
#define WIDTH     32                         // ELL width (P(deg>32) ~ 1e-4, spill net)
#define MAX_SPILL 2048
#define FILL_BLOCKS 4883                     // ceil(NNZ/4/256)
#define CONV_BLOCKS 9375                     // NN*D/8/256 exactly

// fp16 embeddings: e0 (converted), layer-1, layer-2 outputs (38.4 MB each)
__device__ __half g_E0[(size_t)NN * D];
__device__ __half g_A[(size_t)NN * D];
__device__ __half g_B[(size_t)NN * D];

// ELL storage: packed (col_byte_offset, val_bits). 76.8 MB (L2-resident)
// col_byte_offset = col * D * sizeof(__half) = col << 7
__device__ int2 g_ell[(size_t)NN * WIDTH];
__device__ int  g_len[NN];

// Spill safety net (degree > WIDTH; expected ~tens of edges). Raw col here.
__device__ int   g_spill_count;
__device__ int   g_srow[MAX_SPILL];
__device__ int   g_scol[MAX_SPILL];
__device__ float g_sval[MAX_SPILL];

// ---------------------------------------------------------------------------
__global__ void init_kernel() {
    int i = blockIdx.x * blockDim.x + threadIdx.x;
    const int n4 = NN / 4;                    // 75000
    if (i < n4)
        reinterpret_cast<int4*>(g_len)[i] = make_int4(0, 0, 0, 0);
    if (i == 0) g_spill_count = 0;
}

// Combined build kernel: blocks [0, FILL_BLOCKS) run ELL fill (atomic-bound),
// blocks [FILL_BLOCKS, +CONV_BLOCKS) run fp32->fp16 convert (DRAM-bound).
__global__ void build_kernel(const int*   __restrict__ erow,
                             const int*   __restrict__ ecol,
                             const float* __restrict__ evals,
                             const float* __restrict__ uemb,
                             const float* __restrict__ iemb) {
    if (blockIdx.x < FILL_BLOCKS) {
        int t = blockIdx.x * blockDim.x + threadIdx.x;
        int i4 = t * 4;
        if (i4 >= NNZ) return;
        int4   r = __ldcs(reinterpret_cast<const int4*>(erow + i4));
        int4   c = __ldcs(reinterpret_cast<const int4*>(ecol + i4));
        float4 v = __ldcs(reinterpret_cast<const float4*>(evals + i4));
        int    rows[4] = {r.x, r.y, r.z, r.w};
        int    cols[4] = {c.x, c.y, c.z, c.w};
        float  vals[4] = {v.x, v.y, v.z, v.w};
#pragma unroll
        for (int k = 0; k < 4; k++) {
            int pos = atomicAdd(&g_len[rows[k]], 1);
            if (pos < WIDTH) {
                g_ell[(size_t)rows[k] * WIDTH + pos] =
                    make_int2(cols[k] << 7, __float_as_int(vals[k]));
            } else {
                int s = atomicAdd(&g_spill_count, 1);
                if (s < MAX_SPILL) {
                    g_srow[s] = rows[k]; g_scol[s] = cols[k]; g_sval[s] = vals[k];
                }
            }
        }
    } else {
        long long i8 = ((long long)(blockIdx.x - FILL_BLOCKS) * blockDim.x
                        + threadIdx.x) * 8;
        if (i8 >= (long long)NN * D) return;
        const float* src = (i8 < UD) ? (uemb + i8) : (iemb + (i8 - UD));
        float4 a = *reinterpret_cast<const float4*>(src);
        float4 b = *reinterpret_cast<const float4*>(src + 4);
        __half2 h0 = __floats2half2_rn(a.x, a.y);
        __half2 h1 = __floats2half2_rn(a.z, a.w);
        __half2 h2 = __floats2half2_rn(b.x, b.y);
        __half2 h3 = __floats2half2_rn(b.z, b.w);
        uint4 packed = make_uint4(*reinterpret_cast<uint32_t*>(&h0),
                                  *reinterpret_cast<uint32_t*>(&h1),
                                  *reinterpret_cast<uint32_t*>(&h2),
                                  *reinterpret_cast<uint32_t*>(&h3));
        *reinterpret_cast<uint4*>(g_E0 + i8) = packed;
    }
}

// ---------------------------------------------------------------------------
// Warp computes one output row (round-13 proven body). 16 lanes per edge,
// lane owns dims {4*sub .. 4*sub+3}; halves process alternating edges;
// one cross-half shfl reduce at the end. ELL carries PRE-SCALED byte offsets:
// row address = src_base + off + (sub<<3)  (no 64-bit IMAD per edge).
// Padding edges carry off=0, v=0: load row 0 (L1-hot), FMA adds 0.
__device__ __forceinline__ float4 spmm_row_acc_h(int node, int lane,
                                                 const __half* __restrict__ src) {
    int n = min(g_len[node], WIDTH);
    int sub  = lane & 15;
    int half_id = lane >> 4;

    int2 ev = make_int2(0, 0);
    if (lane < n)
        ev = __ldcs(g_ell + (size_t)node * WIDTH + lane);  // evict-first stream

    const char* base = reinterpret_cast<const char*>(src) + (sub << 3);

    float4 acc = make_float4(0.f, 0.f, 0.f, 0.f);
    int n8 = (n + 7) & ~7;                    // <= 32
    for (int j = 0; j < n8; j += 8) {
#pragma unroll
        for (int k = 0; k < 4; k++) {
            int idx = j + 2 * k + half_id;    // this half's edge
            int   off = __shfl_sync(0xFFFFFFFFu, ev.x, idx);
            float vj  = __int_as_float(__shfl_sync(0xFFFFFFFFu, ev.y, idx));
            uint2 raw = *reinterpret_cast<const uint2*>(base + off);
            float2 x0 = __half22float2(*reinterpret_cast<__half2*>(&raw.x));
            float2 x1 = __half22float2(*reinterpret_cast<__half2*>(&raw.y));
            acc.x += vj * x0.x;
            acc.y += vj * x0.y;
            acc.z += vj * x1.x;
            acc.w += vj * x1.y;
        }
    }
    // cross-half reduce: lanes L and L^16 hold partials for the same dims
    acc.x += __shfl_xor_sync(0xFFFFFFFFu, acc.x, 16);
    acc.y += __shfl_xor_sync(0xFFFFFFFFu, acc.y, 16);
    acc.z += __shfl_xor_sync(0xFFFFFFFFu, acc.z, 16);
    acc.w += __shfl_xor_sync(0xFFFFFFFFu, acc.w, 16);
    return acc;
}

// Rare-path (post-reduce): add spill contributions for rows deg > WIDTH.
__device__ __forceinline__ float4 spill_patch_h(int node, int lane, float4 acc,
                                                const __half* __restrict__ src) {
    if (g_len[node] > WIDTH) {                 // ~25 rows in the whole graph
        int sub = lane & 15;
        int cnt = min(g_spill_count, MAX_SPILL);
        for (int s = 0; s < cnt; s++) {
            if (g_srow[s] == node) {
                int   cj = g_scol[s];
                float vj = g_sval[s];
                uint2 raw = *reinterpret_cast<const uint2*>(
                    src + (size_t)cj * D + 4 * sub);
                float2 x0 = __half22float2(*reinterpret_cast<__half2*>(&raw.x));
                float2 x1 = __half22float2(*reinterpret_cast<__half2*>(&raw.y));
                acc.x += vj * x0.x;
                acc.y += vj * x0.y;
                acc.z += vj * x1.x;
                acc.w += vj * x1.y;
            }
        }
    }
    return acc;
}

// Full SpMM (layers 1, 2): one warp per destination row; lanes<16 store 8B each.
__global__ void spmm_ell_kernel(int stage) {
    int warp = (blockIdx.x * blockDim.x + threadIdx.x) >> 5;
    int lane = threadIdx.x & 31;
    if (warp >= NN) return;

    const __half* src = (stage == 0) ? g_E0 : g_A;
    __half*       dst = (stage == 0) ? g_A  : g_B;

    float4 acc = spmm_row_acc_h(warp, lane, src);

    if (lane < 16) {
        __half2 h0 = __floats2half2_rn(acc.x, acc.y);
        __half2 h1 = __floats2half2_rn(acc.z, acc.w);
        uint32_t b0 = *reinterpret_cast<uint32_t*>(&h0);
        uint32_t b1 = *reinterpret_cast<uint32_t*>(&h1);
        asm volatile("st.global.cs.v2.b32 [%0], {%1, %2};"
                     :: "l"(dst + (size_t)warp * D + 4 * lane), "r"(b0), "r"(b1)
                     : "memory");
    }
}

// Spill mop-up (tiny grid, usually no-op): 16 threads/edge, 4 dims each.
__global__ void spill_kernel(int stage) {
    int cnt = min(g_spill_count, MAX_SPILL);
    int idx = blockIdx.x * blockDim.x + threadIdx.x;
    int e = idx >> 4;
    int q = idx & 15;
    if (e >= cnt) return;

    const __half* src = (stage == 0) ? g_E0 : g_A;
    __half*       dst = (stage == 0) ? g_A  : g_B;

    int   row = g_srow[e];
    int   col = g_scol[e];
    float v   = g_sval[e];
    const __half* srow = src + (size_t)col * D + q * 4;
    __half* p = dst + (size_t)row * D + q * 4;
#pragma unroll
    for (int h = 0; h < 2; h++) {
        uint32_t raw = *reinterpret_cast<const uint32_t*>(srow + 2 * h);
        float2 x = __half22float2(*reinterpret_cast<__half2*>(&raw));
        __half2 m = __floats2half2_rn(v * x.x, v * x.y);
        uint32_t mb = *reinterpret_cast<uint32_t*>(&m);
        asm volatile("red.global.add.noftz.f16x2 [%0], %1;"
                     :: "l"(p + 2 * h), "r"(mb) : "memory");
    }
}

// ---------------------------------------------------------------------------
// Fused layer-3 + dot: one warp per pair. e3 computed inline from g_B (fp16).
// e0 endpoint terms read exact fp32 inputs. Lanes<16 own 4 dims each.
__global__ void final_kernel(const int*   __restrict__ users,
                             const int*   __restrict__ items,
                             const float* __restrict__ uemb,
                             const float* __restrict__ iemb,
                             float*       __restrict__ out) {
    int warp = (blockIdx.x * blockDim.x + threadIdx.x) >> 5;
    int lane = threadIdx.x & 31;
    if (warp >= BATCH) return;

    int u  = __ldg(users + warp);
    int it = __ldg(items + warp);
    int nu = u;
    int ni = NUM_USERS + it;

    // e3 at the two endpoints (layer-3 SpMM, inline, fp16 gathers)
    float4 e3u = spmm_row_acc_h(nu, lane, g_B);
    e3u = spill_patch_h(nu, lane, e3u, g_B);
    float4 e3i = spmm_row_acc_h(ni, lane, g_B);
    e3i = spill_patch_h(ni, lane, e3i, g_B);

    float dot = 0.f;
    if (lane < 16) {
        int sub = lane;
        size_t urow = (size_t)nu * D + 4 * sub;
        size_t irow = (size_t)ni * D + 4 * sub;

        uint2 rauh = *reinterpret_cast<const uint2*>(g_A + urow);
        uint2 rbuh = *reinterpret_cast<const uint2*>(g_B + urow);
        uint2 raih = *reinterpret_cast<const uint2*>(g_A + irow);
        uint2 rbih = *reinterpret_cast<const uint2*>(g_B + irow);
        float4 e0u = *reinterpret_cast<const float4*>(uemb + (size_t)u  * D + 4 * sub);
        float4 e0i = *reinterpret_cast<const float4*>(iemb + (size_t)it * D + 4 * sub);

        float2 au0 = __half22float2(*reinterpret_cast<__half2*>(&rauh.x));
        float2 au1 = __half22float2(*reinterpret_cast<__half2*>(&rauh.y));
        float2 bu0 = __half22float2(*reinterpret_cast<__half2*>(&rbuh.x));
        float2 bu1 = __half22float2(*reinterpret_cast<__half2*>(&rbuh.y));
        float2 ai0 = __half22float2(*reinterpret_cast<__half2*>(&raih.x));
        float2 ai1 = __half22float2(*reinterpret_cast<__half2*>(&raih.y));
        float2 bi0 = __half22float2(*reinterpret_cast<__half2*>(&rbih.x));
        float2 bi1 = __half22float2(*reinterpret_cast<__half2*>(&rbih.y));

        float uv0 = e0u.x + au0.x + bu0.x + e3u.x;
        float uv1 = e0u.y + au0.y + bu0.y + e3u.y;
        float uv2 = e0u.z + au1.x + bu1.x + e3u.z;
        float uv3 = e0u.w + au1.y + bu1.y + e3u.w;
        float iv0 = e0i.x + ai0.x + bi0.x + e3i.x;
        float iv1 = e0i.y + ai0.y + bi0.y + e3i.y;
        float iv2 = e0i.z + ai1.x + bi1.x + e3i.z;
        float iv3 = e0i.w + ai1.y + bi1.y + e3i.w;

        dot = uv0 * iv0 + uv1 * iv1 + uv2 * iv2 + uv3 * iv3;
    }
#pragma unroll
    for (int off = 16; off > 0; off >>= 1)
        dot += __shfl_xor_sync(0xFFFFFFFFu, dot, off);

    if (lane == 0) out[warp] = dot * 0.0625f;   // (1/4)*(1/4)
}

// ---------------------------------------------------------------------------
extern "C" void kernel_launch(void* const* d_in, const int* in_sizes, int n_in,
                              void* d_out, int out_size) {
    const int*   users = (const int*)  d_in[0];
    const int*   items = (const int*)  d_in[1];
    const int*   erow  = (const int*)  d_in[2];
    const int*   ecol  = (const int*)  d_in[3];
    const float* evals = (const float*)d_in[4];
    const float* uemb  = (const float*)d_in[5];
    const float* iemb  = (const float*)d_in[6];
    float* out = (float*)d_out;

    // --- init, then overlapped ELL fill + fp16 convert ---
    init_kernel<<<(NN / 4 + 255) / 256, 256>>>();
    build_kernel<<<FILL_BLOCKS + CONV_BLOCKS, 256>>>(erow, ecol, evals, uemb, iemb);

    int threads = 256;                         // 8 warps/block
    int blocks  = (NN + 7) / 8;                // 37500
    int sblocks = (MAX_SPILL * 16) / 256;      // 128

    // --- layers 1,2 full; layer 3 fused into final ---
    spmm_ell_kernel<<<blocks, threads>>>(0);
    spill_kernel<<<sblocks, 256>>>(0);

    spmm_ell_kernel<<<blocks, threads>>>(1);
    spill_kernel<<<sblocks, 256>>>(1);

    // --- fused layer-3 + gather + dot ---
    final_kernel<<<(BATCH + 7) / 8, 256>>>(users, items, uemb, iemb, out);
}

// round 16
// speedup vs baseline: 1.1316x; 1.0276x over previous
#include <cuda_runtime.h>
#include <cuda_fp16.h>
#include <cstdint>

#define NUM_USERS 100000
#define NUM_ITEMS 200000
#define NN        (NUM_USERS + NUM_ITEMS)   // 300000
#define D         64
#define UD        (NUM_USERS * D)           // 6400000
#define NNZ       5000000
#define BATCH     16384
#define WIDTH     32                         // ELL width (P(deg>32) ~ 1e-4, spill net)
#define MAX_SPILL 2048
#define FILL_BLOCKS 4883                     // ceil(NNZ/4/256)
#define CONV_BLOCKS 9375                     // NN*D/8/256 exactly

// fp16 embeddings: e0 (converted), layer-1, layer-2 outputs (38.4 MB each)
__device__ __half g_E0[(size_t)NN * D];
__device__ __half g_A[(size_t)NN * D];
__device__ __half g_B[(size_t)NN * D];

// ELL storage: packed (col, val_bits). 76.8 MB (L2-resident)
__device__ int2 g_ell[(size_t)NN * WIDTH];
__device__ int  g_len[NN];

// Spill safety net (degree > WIDTH; expected ~tens of edges)
__device__ int   g_spill_count;
__device__ int   g_srow[MAX_SPILL];
__device__ int   g_scol[MAX_SPILL];
__device__ float g_sval[MAX_SPILL];

// ---------------------------------------------------------------------------
__global__ void init_kernel() {
    int i = blockIdx.x * blockDim.x + threadIdx.x;
    const int n4 = NN / 4;                    // 75000
    if (i < n4)
        reinterpret_cast<int4*>(g_len)[i] = make_int4(0, 0, 0, 0);
    if (i == 0) g_spill_count = 0;
}

// Combined build kernel: blocks [0, FILL_BLOCKS) run ELL fill (atomic-bound),
// blocks [FILL_BLOCKS, +CONV_BLOCKS) run fp32->fp16 convert (DRAM-bound).
__global__ void build_kernel(const int*   __restrict__ erow,
                             const int*   __restrict__ ecol,
                             const float* __restrict__ evals,
                             const float* __restrict__ uemb,
                             const float* __restrict__ iemb) {
    if (blockIdx.x < FILL_BLOCKS) {
        int t = blockIdx.x * blockDim.x + threadIdx.x;
        int i4 = t * 4;
        if (i4 >= NNZ) return;
        int4   r = __ldcs(reinterpret_cast<const int4*>(erow + i4));
        int4   c = __ldcs(reinterpret_cast<const int4*>(ecol + i4));
        float4 v = __ldcs(reinterpret_cast<const float4*>(evals + i4));
        int    rows[4] = {r.x, r.y, r.z, r.w};
        int    cols[4] = {c.x, c.y, c.z, c.w};
        float  vals[4] = {v.x, v.y, v.z, v.w};
#pragma unroll
        for (int k = 0; k < 4; k++) {
            int pos = atomicAdd(&g_len[rows[k]], 1);
            if (pos < WIDTH) {
                g_ell[(size_t)rows[k] * WIDTH + pos] =
                    make_int2(cols[k], __float_as_int(vals[k]));
            } else {
                int s = atomicAdd(&g_spill_count, 1);
                if (s < MAX_SPILL) {
                    g_srow[s] = rows[k]; g_scol[s] = cols[k]; g_sval[s] = vals[k];
                }
            }
        }
    } else {
        long long i8 = ((long long)(blockIdx.x - FILL_BLOCKS) * blockDim.x
                        + threadIdx.x) * 8;
        if (i8 >= (long long)NN * D) return;
        const float* src = (i8 < UD) ? (uemb + i8) : (iemb + (i8 - UD));
        float4 a = *reinterpret_cast<const float4*>(src);
        float4 b = *reinterpret_cast<const float4*>(src + 4);
        __half2 h0 = __floats2half2_rn(a.x, a.y);
        __half2 h1 = __floats2half2_rn(a.z, a.w);
        __half2 h2 = __floats2half2_rn(b.x, b.y);
        __half2 h3 = __floats2half2_rn(b.z, b.w);
        uint4 packed = make_uint4(*reinterpret_cast<uint32_t*>(&h0),
                                  *reinterpret_cast<uint32_t*>(&h1),
                                  *reinterpret_cast<uint32_t*>(&h2),
                                  *reinterpret_cast<uint32_t*>(&h3));
        *reinterpret_cast<uint4*>(g_E0 + i8) = packed;
    }
}

// ---------------------------------------------------------------------------
// Warp computes one output row (round-13 proven body). 16 lanes per edge,
// lane owns dims {4*sub .. 4*sub+3}; halves process alternating edges;
// one cross-half shfl reduce at the end.
// Padding edges carry c=0, v=0: load row 0 (L1-hot), FMA adds 0.
__device__ __forceinline__ float4 spmm_row_acc_h(int node, int lane,
                                                 const __half* __restrict__ src) {
    int n = min(g_len[node], WIDTH);
    int sub  = lane & 15;
    int half_id = lane >> 4;

    int2 ev = make_int2(0, 0);
    if (lane < n)
        ev = __ldcs(g_ell + (size_t)node * WIDTH + lane);  // evict-first stream

    float4 acc = make_float4(0.f, 0.f, 0.f, 0.f);
    int n8 = (n + 7) & ~7;                    // <= 32
    for (int j = 0; j < n8; j += 8) {
#pragma unroll
        for (int k = 0; k < 4; k++) {
            int idx = j + 2 * k + half_id;    // this half's edge
            int   cj = __shfl_sync(0xFFFFFFFFu, ev.x, idx);
            float vj = __int_as_float(__shfl_sync(0xFFFFFFFFu, ev.y, idx));
            uint2 raw = *reinterpret_cast<const uint2*>(
                src + (size_t)cj * D + 4 * sub);
            float2 x0 = __half22float2(*reinterpret_cast<__half2*>(&raw.x));
            float2 x1 = __half22float2(*reinterpret_cast<__half2*>(&raw.y));
            acc.x += vj * x0.x;
            acc.y += vj * x0.y;
            acc.z += vj * x1.x;
            acc.w += vj * x1.y;
        }
    }
    // cross-half reduce: lanes L and L^16 hold partials for the same dims
    acc.x += __shfl_xor_sync(0xFFFFFFFFu, acc.x, 16);
    acc.y += __shfl_xor_sync(0xFFFFFFFFu, acc.y, 16);
    acc.z += __shfl_xor_sync(0xFFFFFFFFu, acc.z, 16);
    acc.w += __shfl_xor_sync(0xFFFFFFFFu, acc.w, 16);
    return acc;
}

// Rare-path (post-reduce): add spill contributions for rows deg > WIDTH.
__device__ __forceinline__ float4 spill_patch_h(int node, int lane, float4 acc,
                                                const __half* __restrict__ src) {
    if (g_len[node] > WIDTH) {                 // ~25 rows in the whole graph
        int sub = lane & 15;
        int cnt = min(g_spill_count, MAX_SPILL);
        for (int s = 0; s < cnt; s++) {
            if (g_srow[s] == node) {
                int   cj = g_scol[s];
                float vj = g_sval[s];
                uint2 raw = *reinterpret_cast<const uint2*>(
                    src + (size_t)cj * D + 4 * sub);
                float2 x0 = __half22float2(*reinterpret_cast<__half2*>(&raw.x));
                float2 x1 = __half22float2(*reinterpret_cast<__half2*>(&raw.y));
                acc.x += vj * x0.x;
                acc.y += vj * x0.y;
                acc.z += vj * x1.x;
                acc.w += vj * x1.y;
            }
        }
    }
    return acc;
}

// Full SpMM (layers 1, 2): one warp per destination row; lanes<16 store 8B each.
__global__ void spmm_ell_kernel(int stage) {
    int warp = (blockIdx.x * blockDim.x + threadIdx.x) >> 5;
    int lane = threadIdx.x & 31;
    if (warp >= NN) return;

    const __half* src = (stage == 0) ? g_E0 : g_A;
    __half*       dst = (stage == 0) ? g_A  : g_B;

    float4 acc = spmm_row_acc_h(warp, lane, src);

    if (lane < 16) {
        __half2 h0 = __floats2half2_rn(acc.x, acc.y);
        __half2 h1 = __floats2half2_rn(acc.z, acc.w);
        uint32_t b0 = *reinterpret_cast<uint32_t*>(&h0);
        uint32_t b1 = *reinterpret_cast<uint32_t*>(&h1);
        asm volatile("st.global.cs.v2.b32 [%0], {%1, %2};"
                     :: "l"(dst + (size_t)warp * D + 4 * lane), "r"(b0), "r"(b1)
                     : "memory");
    }
}

// Spill mop-up: grid-stride over spill edges, 16 threads/edge, 4 dims each.
// Small grid (16 blocks) — list is ~tens of entries; loop covers MAX_SPILL.
__global__ void spill_kernel(int stage) {
    int cnt = min(g_spill_count, MAX_SPILL);
    int total = cnt * 16;

    const __half* src = (stage == 0) ? g_E0 : g_A;
    __half*       dst = (stage == 0) ? g_A  : g_B;

    for (int idx = blockIdx.x * blockDim.x + threadIdx.x;
         idx < total;
         idx += gridDim.x * blockDim.x) {
        int e = idx >> 4;
        int q = idx & 15;
        int   row = g_srow[e];
        int   col = g_scol[e];
        float v   = g_sval[e];
        const __half* srow = src + (size_t)col * D + q * 4;
        __half* p = dst + (size_t)row * D + q * 4;
#pragma unroll
        for (int h = 0; h < 2; h++) {
            uint32_t raw = *reinterpret_cast<const uint32_t*>(srow + 2 * h);
            float2 x = __half22float2(*reinterpret_cast<__half2*>(&raw));
            __half2 m = __floats2half2_rn(v * x.x, v * x.y);
            uint32_t mb = *reinterpret_cast<uint32_t*>(&m);
            asm volatile("red.global.add.noftz.f16x2 [%0], %1;"
                         :: "l"(p + 2 * h), "r"(mb) : "memory");
        }
    }
}

// ---------------------------------------------------------------------------
// Fused layer-3 + dot: one warp per pair. e3 computed inline from g_B (fp16).
// e0 endpoint terms read exact fp32 inputs. Lanes<16 own 4 dims each.
__global__ void final_kernel(const int*   __restrict__ users,
                             const int*   __restrict__ items,
                             const float* __restrict__ uemb,
                             const float* __restrict__ iemb,
                             float*       __restrict__ out) {
    int warp = (blockIdx.x * blockDim.x + threadIdx.x) >> 5;
    int lane = threadIdx.x & 31;
    if (warp >= BATCH) return;

    int u  = __ldg(users + warp);
    int it = __ldg(items + warp);
    int nu = u;
    int ni = NUM_USERS + it;

    // e3 at the two endpoints (layer-3 SpMM, inline, fp16 gathers)
    float4 e3u = spmm_row_acc_h(nu, lane, g_B);
    e3u = spill_patch_h(nu, lane, e3u, g_B);
    float4 e3i = spmm_row_acc_h(ni, lane, g_B);
    e3i = spill_patch_h(ni, lane, e3i, g_B);

    float dot = 0.f;
    if (lane < 16) {
        int sub = lane;
        size_t urow = (size_t)nu * D + 4 * sub;
        size_t irow = (size_t)ni * D + 4 * sub;

        uint2 rauh = *reinterpret_cast<const uint2*>(g_A + urow);
        uint2 rbuh = *reinterpret_cast<const uint2*>(g_B + urow);
        uint2 raih = *reinterpret_cast<const uint2*>(g_A + irow);
        uint2 rbih = *reinterpret_cast<const uint2*>(g_B + irow);
        float4 e0u = *reinterpret_cast<const float4*>(uemb + (size_t)u  * D + 4 * sub);
        float4 e0i = *reinterpret_cast<const float4*>(iemb + (size_t)it * D + 4 * sub);

        float2 au0 = __half22float2(*reinterpret_cast<__half2*>(&rauh.x));
        float2 au1 = __half22float2(*reinterpret_cast<__half2*>(&rauh.y));
        float2 bu0 = __half22float2(*reinterpret_cast<__half2*>(&rbuh.x));
        float2 bu1 = __half22float2(*reinterpret_cast<__half2*>(&rbuh.y));
        float2 ai0 = __half22float2(*reinterpret_cast<__half2*>(&raih.x));
        float2 ai1 = __half22float2(*reinterpret_cast<__half2*>(&raih.y));
        float2 bi0 = __half22float2(*reinterpret_cast<__half2*>(&rbih.x));
        float2 bi1 = __half22float2(*reinterpret_cast<__half2*>(&rbih.y));

        float uv0 = e0u.x + au0.x + bu0.x + e3u.x;
        float uv1 = e0u.y + au0.y + bu0.y + e3u.y;
        float uv2 = e0u.z + au1.x + bu1.x + e3u.z;
        float uv3 = e0u.w + au1.y + bu1.y + e3u.w;
        float iv0 = e0i.x + ai0.x + bi0.x + e3i.x;
        float iv1 = e0i.y + ai0.y + bi0.y + e3i.y;
        float iv2 = e0i.z + ai1.x + bi1.x + e3i.z;
        float iv3 = e0i.w + ai1.y + bi1.y + e3i.w;

        dot = uv0 * iv0 + uv1 * iv1 + uv2 * iv2 + uv3 * iv3;
    }
#pragma unroll
    for (int off = 16; off > 0; off >>= 1)
        dot += __shfl_xor_sync(0xFFFFFFFFu, dot, off);

    if (lane == 0) out[warp] = dot * 0.0625f;   // (1/4)*(1/4)
}

// ---------------------------------------------------------------------------
extern "C" void kernel_launch(void* const* d_in, const int* in_sizes, int n_in,
                              void* d_out, int out_size) {
    const int*   users = (const int*)  d_in[0];
    const int*   items = (const int*)  d_in[1];
    const int*   erow  = (const int*)  d_in[2];
    const int*   ecol  = (const int*)  d_in[3];
    const float* evals = (const float*)d_in[4];
    const float* uemb  = (const float*)d_in[5];
    const float* iemb  = (const float*)d_in[6];
    float* out = (float*)d_out;

    // --- init, then overlapped ELL fill + fp16 convert ---
    init_kernel<<<(NN / 4 + 255) / 256, 256>>>();
    build_kernel<<<FILL_BLOCKS + CONV_BLOCKS, 256>>>(erow, ecol, evals, uemb, iemb);

    int threads = 256;                         // 8 warps/block
    int blocks  = (NN + 7) / 8;                // 37500

    // --- layers 1,2 full; layer 3 fused into final ---
    spmm_ell_kernel<<<blocks, threads>>>(0);
    spill_kernel<<<16, 256>>>(0);

    spmm_ell_kernel<<<blocks, threads>>>(1);
    spill_kernel<<<16, 256>>>(1);

    // --- fused layer-3 + gather + dot ---
    final_kernel<<<(BATCH + 7) / 8, 256>>>(users, items, uemb, iemb, out);
}